// round 15
// baseline (speedup 1.0000x reference)
#include <cuda_runtime.h>
#include <cuda_fp16.h>
#include <cstdint>
#include <math.h>

#define N_NODES 65536
#define C       256
#define B       8
#define EMB     512
#define NET     7
#define NNT     7
#define E_EDGES (N_NODES * 7)
#define NCOLS   (NET * C)      /* 1792 */
#define EPS     1e-5f

// ---------------- scratch (device globals; zero-initialized at load) ----------------
__device__ __align__(128) __half g_hh[(size_t)N_NODES * C];     // GN out fp16, row-major
__device__ float    g_h2[(size_t)N_NODES * C];                  // conv1 out + emb (fp32)
__device__ __align__(128) __half g_Y[(size_t)N_NODES * NCOLS];  // GEMM out (235 MB, fp16)
__device__ __align__(128) __half g_Wh[2][(size_t)NCOLS * C];    // transposed fp16 weights [n][k]
__device__ float    g_TB[2][NET * NNT * C];                     // one-hot bias tables
__device__ float    g_S[B * C];
__device__ float    g_S2[B * C];
__device__ int      g_cnt[B];
__device__ int      g_done;
__device__ float    g_mean[B * C];
__device__ float    g_istd[B * C];
__device__ float    g_emb[B * C];
__device__ int      g_deg[N_NODES];
__device__ int      g_fill[N_NODES];
__device__ int      g_rp[N_NODES];
__device__ int      g_bsum[256];
__device__ unsigned g_ct[E_EDGES];

// ---------------- helpers ----------------
__device__ __forceinline__ float silu(float z) { return z / (1.0f + __expf(-z)); }

__device__ __forceinline__ uint32_t smem_u32(const void* p) {
    uint32_t a;
    asm("{ .reg .u64 t; cvta.to.shared.u64 t, %1; cvt.u32.u64 %0, t; }" : "=r"(a) : "l"(p));
    return a;
}
__device__ __forceinline__ void mma16(float* d, const uint32_t* a, uint32_t b0, uint32_t b1) {
    asm volatile(
        "mma.sync.aligned.m16n8k16.row.col.f32.f16.f16.f32 "
        "{%0,%1,%2,%3}, {%4,%5,%6,%7}, {%8,%9}, {%0,%1,%2,%3};"
        : "+f"(d[0]), "+f"(d[1]), "+f"(d[2]), "+f"(d[3])
        : "r"(a[0]), "r"(a[1]), "r"(a[2]), "r"(a[3]), "r"(b0), "r"(b1));
}
__device__ __forceinline__ void ldsm4(uint32_t& r0, uint32_t& r1, uint32_t& r2, uint32_t& r3,
                                      uint32_t addr) {
    asm volatile("ldmatrix.sync.aligned.m8n8.x4.shared.b16 {%0,%1,%2,%3}, [%4];"
                 : "=r"(r0), "=r"(r1), "=r"(r2), "=r"(r3) : "r"(addr));
}
__device__ __forceinline__ void cpa16(uint32_t dst, const void* src) {
    asm volatile("cp.async.cg.shared.global [%0], [%1], 16;" :: "r"(dst), "l"(src));
}

// ---------------- zero deg/fill ----------------
__global__ void zero_df(int* deg, int* fill) {
    int i = blockIdx.x * 256 + threadIdx.x;
    deg[i] = 0;
    fill[i] = 0;
}

// ---------------- weight restructure (transpose + TB) ----------------
// Wh[n][k] = half(cw[(t*263+k)*256+o]),  n = t*256+o, k<256
__global__ void build_w(const float* __restrict__ cw, __half* __restrict__ Wh,
                        float* __restrict__ TB) {
    __shared__ float tile[32][33];
    const int tx = threadIdx.x;   // 32
    const int ty = threadIdx.y;   // 8
    const int by = blockIdx.y;    // 56
    const int t  = by >> 3;
    const int o0 = (by & 7) * 32;
    if (blockIdx.x < 8) {
        const int k0 = blockIdx.x * 32;
        for (int ki = ty; ki < 32; ki += 8)
            tile[ki][tx] = cw[(size_t)(t * 263 + k0 + ki) * C + o0 + tx];
        __syncthreads();
        for (int r = ty; r < 32; r += 8)
            Wh[(size_t)(t * 256 + o0 + r) * C + k0 + tx] = __float2half_rn(tile[tx][r]);
    } else {
        if (ty < NNT)
            TB[(size_t)(t * NNT + ty) * C + o0 + tx] =
                cw[(size_t)(t * 263 + 256 + ty) * C + o0 + tx];
    }
}

// ---------------- group norm: stats + fused last-block finalize ----------------
__global__ void gn_stats_f(const float* __restrict__ x, const int* __restrict__ bid,
                           float* S, float* S2, int* cnt,
                           float* meanA, float* istdA) {
    const int c  = threadIdx.x;
    const int n0 = blockIdx.x * 128;
    float s = 0.0f, s2 = 0.0f;
    int curb = bid[n0];
    int lc = 0;
    for (int n = n0; n < n0 + 128; n++) {
        int b = bid[n];
        if (b != curb) {
            atomicAdd(&S[curb * C + c], s);
            atomicAdd(&S2[curb * C + c], s2);
            if (c == 0) atomicAdd(&cnt[curb], lc);
            s = 0.0f; s2 = 0.0f; lc = 0; curb = b;
        }
        float v = x[(size_t)n * C + c];
        s += v; s2 += v * v; lc++;
    }
    atomicAdd(&S[curb * C + c], s);
    atomicAdd(&S2[curb * C + c], s2);
    if (c == 0) atomicAdd(&cnt[curb], lc);

    __threadfence();
    __shared__ int isLast;
    __shared__ float sS[C], sS2[C];
    if (c == 0) isLast = (atomicAdd(&g_done, 1) == gridDim.x - 1);
    __syncthreads();
    if (!isLast) return;
    for (int b = 0; b < B; b++) {
        int cb = cnt[b];
        sS[c]  = S[b * C + c];
        sS2[c] = S2[b * C + c];
        __syncthreads();
        const int g0 = (c >> 3) << 3;
        float Sg = 0.0f, S2g = 0.0f;
#pragma unroll
        for (int j = 0; j < 8; j++) { Sg += sS[g0 + j]; S2g += sS2[g0 + j]; }
        float count = (float)cb * 8.0f;
        float ic  = 1.0f / (count + EPS);
        float mu  = Sg * ic;
        float var = (S2g - 2.0f * mu * Sg + count * mu * mu) * ic;
        meanA[b * C + c] = mu;
        istdA[b * C + c] = 1.0f / sqrtf(var + EPS);
        S[b * C + c]  = 0.0f;
        S2[b * C + c] = 0.0f;
        if (c == 0) cnt[b] = 0;
        __syncthreads();
    }
    if (c == 0) g_done = 0;
}

// grid = N, block = 256: out_half = silu((x - mean)*istd*w + b), row-major
__global__ void gn_norm_silu(const float* __restrict__ x, const int* __restrict__ bid,
                             const float* __restrict__ meanA, const float* __restrict__ istdA,
                             const float* __restrict__ w, const float* __restrict__ bb,
                             __half* __restrict__ out) {
    const int i = blockIdx.x;
    const int c = threadIdx.x;
    const int b = bid[i];
    float v = x[(size_t)i * C + c];
    float z = (v - meanA[b * C + c]) * istdA[b * C + c] * w[c] + bb[c];
    out[(size_t)i * C + c] = __float2half_rn(silu(z));
}

// ---------------- CSR build ----------------
__global__ void csr_deg(const int* __restrict__ ei, int* deg) {
    int e = blockIdx.x * 256 + threadIdx.x;
    if (e < E_EDGES) atomicAdd(&deg[ei[e]], 1);
}
__global__ void scan1(const int* __restrict__ deg, int* rp, int* bsum) {
    __shared__ int sm[256];
    int t = threadIdx.x;
    int i = blockIdx.x * 256 + t;
    int v = deg[i];
    sm[t] = v;
    __syncthreads();
    for (int off = 1; off < 256; off <<= 1) {
        int add = (t >= off) ? sm[t - off] : 0;
        __syncthreads();
        sm[t] += add;
        __syncthreads();
    }
    rp[i] = sm[t] - v;
    if (t == 255) bsum[blockIdx.x] = sm[255];
}
__global__ void scan2(int* bsum) {
    __shared__ int sm[256];
    int t = threadIdx.x;
    int v = bsum[t];
    sm[t] = v;
    __syncthreads();
    for (int off = 1; off < 256; off <<= 1) {
        int add = (t >= off) ? sm[t - off] : 0;
        __syncthreads();
        sm[t] += add;
        __syncthreads();
    }
    bsum[t] = sm[t] - v;
}
__global__ void scan3(int* rp, const int* __restrict__ bsum) {
    int i = blockIdx.x * 256 + threadIdx.x;
    rp[i] += bsum[blockIdx.x];
}
__global__ void csr_fill(const int* __restrict__ ei, const int* __restrict__ et,
                         const int* __restrict__ rp, int* fill, unsigned* ct) {
    int e = blockIdx.x * 256 + threadIdx.x;
    if (e < E_EDGES) {
        int row = ei[e];
        int col = ei[E_EDGES + e];
        int t   = et[e];
        int pos = rp[row] + atomicAdd(&fill[row], 1);
        ct[pos] = (unsigned)col | ((unsigned)t << 16);
    }
}

// ---------------- emb projection ----------------
__global__ void emb_proj(const float* __restrict__ emb, const float* __restrict__ ew,
                         const float* __restrict__ eb, float* __restrict__ out) {
    __shared__ float se[EMB];
    const int b = blockIdx.x;
    const int o = threadIdx.x;
    for (int k = o; k < EMB; k += 256) se[k] = silu(emb[b * EMB + k]);
    __syncthreads();
    float acc = eb[o];
#pragma unroll 8
    for (int k = 0; k < EMB; k++) acc += se[k] * ew[k * C + o];
    out[b * C + o] = acc;
}

// ---------------- GEMM: Y[N,1792] = hh[N,256] @ Wh^T + TB[nt[row]] ----------------
// fp16 in, fp32 acc; ldmatrix fragments; cp.async tile loads; SW128 XOR swizzle.
#define KC 64   /* K chunk (halves); 128 B per row */

__global__ void __launch_bounds__(256, 2)
gemm_fp16(const __half* __restrict__ hh, const __half* __restrict__ Wh,
          const float* __restrict__ TB, const int* __restrict__ ntype,
          __half* __restrict__ Y) {
    __shared__ __align__(128) __half As[128 * KC];   // 16 KB
    __shared__ __align__(128) __half Bs[128 * KC];   // 16 KB
    __shared__ float TBs[NNT * 128];                  // 3.5 KB

    const int tid  = threadIdx.x;
    const int lane = tid & 31;
    const int warp = tid >> 5;
    const int wm = warp & 3, wn = warp >> 2;

    const int rowBase = blockIdx.y * 128;
    const int nBase   = blockIdx.x * 128;
    const int tEdge   = blockIdx.x >> 1;
    const int oInT    = (blockIdx.x & 1) * 128;

    for (int idx = tid; idx < NNT * 128; idx += 256) {
        TBs[idx] = TB[(size_t)(tEdge * NNT + (idx >> 7)) * C + oInT + (idx & 127)];
    }

    float acc[2][8][4];
#pragma unroll
    for (int a = 0; a < 2; a++)
#pragma unroll
        for (int b2 = 0; b2 < 8; b2++)
#pragma unroll
            for (int c2 = 0; c2 < 4; c2++) acc[a][b2][c2] = 0.0f;

    const uint32_t sA = smem_u32(As), sB = smem_u32(Bs);

    // loader geometry: thread -> (row lr, 4 x 16B segments)
    const int lr    = tid & 127;
    const int hseg  = tid >> 7;            // 0/1 -> segs 0-3 / 4-7
    const uint32_t swrow = (uint32_t)((lr & 7) << 3);

    // ldmatrix per-lane geometry
    const int dr = ((lane >> 3) & 1) * 8 + (lane & 7);
    const int dk = (lane >> 4) << 3;
    uint32_t abase[2], swa[2];
#pragma unroll
    for (int mf = 0; mf < 2; mf++) {
        int r = wm * 32 + mf * 16 + dr;
        abase[mf] = sA + (uint32_t)(r * (KC * 2));
        swa[mf]   = (uint32_t)((r & 7) << 3);
    }
    uint32_t bbase[4], swb[4];
#pragma unroll
    for (int p = 0; p < 4; p++) {
        int n = wn * 64 + p * 16 + dr;
        bbase[p] = sB + (uint32_t)(n * (KC * 2));
        swb[p]   = (uint32_t)((n & 7) << 3);
    }

    for (int c = 0; c < C / KC; c++) {
        const int k0 = c * KC;
        // async tile loads: 8 x 16B per thread
#pragma unroll
        for (int q = 0; q < 4; q++) {
            int s = hseg * 4 + q;
            uint32_t soff = (uint32_t)(lr * (KC * 2)) + (uint32_t)((((s * 8) ^ swrow)) * 2);
            cpa16(sA + soff, hh + (size_t)(rowBase + lr) * C + k0 + s * 8);
            cpa16(sB + soff, Wh + (size_t)(nBase + lr) * C + k0 + s * 8);
        }
        asm volatile("cp.async.commit_group;");
        asm volatile("cp.async.wait_group 0;");
        __syncthreads();

#pragma unroll
        for (int kk = 0; kk < KC; kk += 16) {
            uint32_t af[2][4];
#pragma unroll
            for (int mf = 0; mf < 2; mf++) {
                uint32_t addr = abase[mf] + (uint32_t)((((kk + dk) ^ swa[mf])) * 2);
                ldsm4(af[mf][0], af[mf][1], af[mf][2], af[mf][3], addr);
            }
            uint32_t bf[4][4];
#pragma unroll
            for (int p = 0; p < 4; p++) {
                uint32_t addr = bbase[p] + (uint32_t)((((kk + dk) ^ swb[p])) * 2);
                ldsm4(bf[p][0], bf[p][1], bf[p][2], bf[p][3], addr);
            }
#pragma unroll
            for (int mf = 0; mf < 2; mf++)
#pragma unroll
                for (int nf = 0; nf < 8; nf++) {
                    int p = nf >> 1, o = nf & 1;
                    mma16(acc[mf][nf], af[mf], bf[p][o], bf[p][o + 2]);
                }
        }
        __syncthreads();
    }

    // epilogue: add one-hot bias table, store fp16
    const int gID = lane >> 2, tig = lane & 3;
#pragma unroll
    for (int mf = 0; mf < 2; mf++) {
        int rLo = rowBase + wm * 32 + mf * 16 + gID;
        int rHi = rLo + 8;
        int ntLo = ntype[rLo];
        int ntHi = ntype[rHi];
#pragma unroll
        for (int nf = 0; nf < 8; nf++) {
            int colL = wn * 64 + nf * 8 + tig * 2;
            int colG = nBase + colL;
            __half2 lo = __floats2half2_rn(acc[mf][nf][0] + TBs[ntLo * 128 + colL],
                                           acc[mf][nf][1] + TBs[ntLo * 128 + colL + 1]);
            __half2 hi = __floats2half2_rn(acc[mf][nf][2] + TBs[ntHi * 128 + colL],
                                           acc[mf][nf][3] + TBs[ntHi * 128 + colL + 1]);
            *(__half2*)&Y[(size_t)rLo * NCOLS + colG] = lo;
            *(__half2*)&Y[(size_t)rHi * NCOLS + colG] = hi;
        }
    }
}

// ---------------- gather: out[i,c] = base + sum_e Y[col_e, t_e*256+c] ----------------
// 64 threads/block; each thread owns 4 channels (uint2 = 4 halves per edge).
__global__ void gather_add(const __half* __restrict__ Y, const int* __restrict__ rp,
                           const int* __restrict__ deg, const unsigned* __restrict__ ct,
                           const int* __restrict__ bid,
                           const float* __restrict__ addB,
                           const float* __restrict__ addN,
                           float* __restrict__ out) {
    const int i  = blockIdx.x;
    const int c0 = threadIdx.x * 4;
    const int s = rp[i];
    const int d = deg[i];
    float4 acc;
    if (addB) acc = *(const float4*)(addB + bid[i] * C + c0);
    else      acc = *(const float4*)(addN + (size_t)i * C + c0);
    int e = s;
    for (; e + 1 < s + d; e += 2) {
        unsigned p0 = ct[e], p1 = ct[e + 1];
        uint2 v0 = *(const uint2*)(Y + (size_t)(p0 & 0xFFFF) * NCOLS + (p0 >> 16) * C + c0);
        uint2 v1 = *(const uint2*)(Y + (size_t)(p1 & 0xFFFF) * NCOLS + (p1 >> 16) * C + c0);
        float2 f;
        f = __half22float2(*(__half2*)&v0.x); acc.x += f.x; acc.y += f.y;
        f = __half22float2(*(__half2*)&v0.y); acc.z += f.x; acc.w += f.y;
        f = __half22float2(*(__half2*)&v1.x); acc.x += f.x; acc.y += f.y;
        f = __half22float2(*(__half2*)&v1.y); acc.z += f.x; acc.w += f.y;
    }
    if (e < s + d) {
        unsigned p = ct[e];
        uint2 v = *(const uint2*)(Y + (size_t)(p & 0xFFFF) * NCOLS + (p >> 16) * C + c0);
        float2 f;
        f = __half22float2(*(__half2*)&v.x); acc.x += f.x; acc.y += f.y;
        f = __half22float2(*(__half2*)&v.y); acc.z += f.x; acc.w += f.y;
    }
    *(float4*)(out + (size_t)i * C + c0) = acc;
}

// ---------------- host ----------------
extern "C" void kernel_launch(void* const* d_in, const int* in_sizes, int n_in,
                              void* d_out, int out_size) {
    const float* x       = (const float*)d_in[0];
    const float* emb     = (const float*)d_in[1];
    const int*   bid     = (const int*)d_in[2];
    const int*   ei      = (const int*)d_in[3];
    const int*   et      = (const int*)d_in[4];
    const int*   ntype   = (const int*)d_in[5];
    const float* gn1_w   = (const float*)d_in[6];
    const float* gn1_b   = (const float*)d_in[7];
    const float* conv1_w = (const float*)d_in[8];
    const float* emb_w   = (const float*)d_in[9];
    const float* emb_b   = (const float*)d_in[10];
    const float* gn2_w   = (const float*)d_in[11];
    const float* gn2_b   = (const float*)d_in[12];
    const float* conv2_w = (const float*)d_in[13];
    float* out = (float*)d_out;

    float *S, *S2, *meanA, *istdA, *h2, *embO, *TBa;
    __half *hh, *Y, *Wha;
    int *cnt, *deg, *fill, *rp, *bsum;
    unsigned* ct;
    cudaGetSymbolAddress((void**)&S,     g_S);
    cudaGetSymbolAddress((void**)&S2,    g_S2);
    cudaGetSymbolAddress((void**)&cnt,   g_cnt);
    cudaGetSymbolAddress((void**)&meanA, g_mean);
    cudaGetSymbolAddress((void**)&istdA, g_istd);
    cudaGetSymbolAddress((void**)&hh,    g_hh);
    cudaGetSymbolAddress((void**)&h2,    g_h2);
    cudaGetSymbolAddress((void**)&Y,     g_Y);
    cudaGetSymbolAddress((void**)&Wha,   g_Wh);
    cudaGetSymbolAddress((void**)&TBa,   g_TB);
    cudaGetSymbolAddress((void**)&embO,  g_emb);
    cudaGetSymbolAddress((void**)&deg,   g_deg);
    cudaGetSymbolAddress((void**)&fill,  g_fill);
    cudaGetSymbolAddress((void**)&rp,    g_rp);
    cudaGetSymbolAddress((void**)&bsum,  g_bsum);
    cudaGetSymbolAddress((void**)&ct,    g_ct);

    __half* Wh1 = Wha;
    __half* Wh2 = Wha + (size_t)NCOLS * C;
    float*  TB1 = TBa;
    float*  TB2 = TBa + NET * NNT * C;

    dim3 wgrid(9, 56), wblk(32, 8);
    dim3 ggrid(NCOLS / 128, N_NODES / 128);  // (14, 512)

    build_w<<<wgrid, wblk>>>(conv1_w, Wh1, TB1);                               // 0
    gn_stats_f<<<512, 256>>>(x, bid, S, S2, cnt, meanA, istdA);                // 1
    gn_norm_silu<<<N_NODES, 256>>>(x, bid, meanA, istdA, gn1_w, gn1_b, hh);    // 2
    gemm_fp16<<<ggrid, 256>>>(hh, Wh1, TB1, ntype, Y);                         // 3
    zero_df<<<N_NODES / 256, 256>>>(deg, fill);                                // 4
    csr_deg<<<E_EDGES / 256, 256>>>(ei, deg);                                  // 5
    scan1<<<256, 256>>>(deg, rp, bsum);                                        // 6
    scan2<<<1, 256>>>(bsum);                                                   // 7
    scan3<<<256, 256>>>(rp, bsum);                                             // 8
    csr_fill<<<E_EDGES / 256, 256>>>(ei, et, rp, fill, ct);                    // 9
    emb_proj<<<B, 256>>>(emb, emb_w, emb_b, embO);                             // 10
    gather_add<<<N_NODES, 64>>>(Y, rp, deg, ct, bid, embO, nullptr, h2);       // 11
    gn_stats_f<<<512, 256>>>(h2, bid, S, S2, cnt, meanA, istdA);               // 12
    gn_norm_silu<<<N_NODES, 256>>>(h2, bid, meanA, istdA, gn2_w, gn2_b, hh);   // 13
    build_w<<<wgrid, wblk>>>(conv2_w, Wh2, TB2);                               // 14
    gemm_fp16<<<ggrid, 256>>>(hh, Wh2, TB2, ntype, Y);                         // 15
    gather_add<<<N_NODES, 64>>>(Y, rp, deg, ct, bid, nullptr, x, out);         // 16

    (void)in_sizes; (void)n_in; (void)out_size;
}

// round 17
// speedup vs baseline: 1.4420x; 1.4420x over previous
#include <cuda_runtime.h>
#include <cuda_fp16.h>
#include <cstdint>
#include <math.h>

#define N_NODES 65536
#define C       256
#define B       8
#define EMB     512
#define NET     7
#define NNT     7
#define E_EDGES (N_NODES * 7)
#define NCOLS   (NET * C)      /* 1792 */
#define EPS     1e-5f

// ---------------- scratch (device globals; zero-initialized at load) ----------------
__device__ __align__(128) __half g_hh[(size_t)N_NODES * C];     // GN out fp16, row-major
__device__ float    g_h2[(size_t)N_NODES * C];                  // conv1 out + emb (fp32)
__device__ __align__(128) __half g_Y[(size_t)N_NODES * NCOLS];  // GEMM out (235 MB, fp16)
__device__ __align__(128) __half g_Wh[2][(size_t)NCOLS * C];    // transposed fp16 weights [n][k]
__device__ float    g_TB[2][NET * NNT * C];                     // one-hot bias tables
__device__ float    g_S[B * C];
__device__ float    g_S2[B * C];
__device__ int      g_cnt[B];
__device__ int      g_done;
__device__ float    g_mean[B * C];
__device__ float    g_istd[B * C];
__device__ float    g_emb[B * C];
__device__ int      g_deg[N_NODES];
__device__ int      g_fill[N_NODES];
__device__ int      g_rp[N_NODES];
__device__ int      g_bsum[256];
__device__ unsigned g_ct[E_EDGES];

// ---------------- helpers ----------------
__device__ __forceinline__ float silu(float z) { return z / (1.0f + __expf(-z)); }

__device__ __forceinline__ uint32_t smem_u32(const void* p) {
    uint32_t a;
    asm("{ .reg .u64 t; cvta.to.shared.u64 t, %1; cvt.u32.u64 %0, t; }" : "=r"(a) : "l"(p));
    return a;
}
__device__ __forceinline__ void mma16(float* d, const uint32_t* a, uint32_t b0, uint32_t b1) {
    asm volatile(
        "mma.sync.aligned.m16n8k16.row.col.f32.f16.f16.f32 "
        "{%0,%1,%2,%3}, {%4,%5,%6,%7}, {%8,%9}, {%0,%1,%2,%3};"
        : "+f"(d[0]), "+f"(d[1]), "+f"(d[2]), "+f"(d[3])
        : "r"(a[0]), "r"(a[1]), "r"(a[2]), "r"(a[3]), "r"(b0), "r"(b1));
}
__device__ __forceinline__ void ldsm4(uint32_t& r0, uint32_t& r1, uint32_t& r2, uint32_t& r3,
                                      uint32_t addr) {
    asm volatile("ldmatrix.sync.aligned.m8n8.x4.shared.b16 {%0,%1,%2,%3}, [%4];"
                 : "=r"(r0), "=r"(r1), "=r"(r2), "=r"(r3) : "r"(addr));
}
__device__ __forceinline__ void cpa16(uint32_t dst, const void* src) {
    asm volatile("cp.async.cg.shared.global [%0], [%1], 16;" :: "r"(dst), "l"(src));
}

// ---------------- zero deg/fill ----------------
__global__ void zero_df(int* deg, int* fill) {
    int i = blockIdx.x * 256 + threadIdx.x;
    deg[i] = 0;
    fill[i] = 0;
}

// ---------------- weight restructure (transpose + TB) ----------------
__global__ void build_w(const float* __restrict__ cw, __half* __restrict__ Wh,
                        float* __restrict__ TB) {
    __shared__ float tile[32][33];
    const int tx = threadIdx.x;   // 32
    const int ty = threadIdx.y;   // 8
    const int by = blockIdx.y;    // 56
    const int t  = by >> 3;
    const int o0 = (by & 7) * 32;
    if (blockIdx.x < 8) {
        const int k0 = blockIdx.x * 32;
        for (int ki = ty; ki < 32; ki += 8)
            tile[ki][tx] = cw[(size_t)(t * 263 + k0 + ki) * C + o0 + tx];
        __syncthreads();
        for (int r = ty; r < 32; r += 8)
            Wh[(size_t)(t * 256 + o0 + r) * C + k0 + tx] = __float2half_rn(tile[tx][r]);
    } else {
        if (ty < NNT)
            TB[(size_t)(t * NNT + ty) * C + o0 + tx] =
                cw[(size_t)(t * 263 + 256 + ty) * C + o0 + tx];
    }
}

// ---------------- group norm: stats + fused last-block finalize ----------------
__global__ void gn_stats_f(const float* __restrict__ x, const int* __restrict__ bid,
                           float* S, float* S2, int* cnt,
                           float* meanA, float* istdA) {
    const int c  = threadIdx.x;
    const int n0 = blockIdx.x * 128;
    float s = 0.0f, s2 = 0.0f;
    int curb = bid[n0];
    int lc = 0;
    for (int n = n0; n < n0 + 128; n++) {
        int b = bid[n];
        if (b != curb) {
            atomicAdd(&S[curb * C + c], s);
            atomicAdd(&S2[curb * C + c], s2);
            if (c == 0) atomicAdd(&cnt[curb], lc);
            s = 0.0f; s2 = 0.0f; lc = 0; curb = b;
        }
        float v = x[(size_t)n * C + c];
        s += v; s2 += v * v; lc++;
    }
    atomicAdd(&S[curb * C + c], s);
    atomicAdd(&S2[curb * C + c], s2);
    if (c == 0) atomicAdd(&cnt[curb], lc);

    __threadfence();
    __shared__ int isLast;
    __shared__ float sS[C], sS2[C];
    if (c == 0) isLast = (atomicAdd(&g_done, 1) == gridDim.x - 1);
    __syncthreads();
    if (!isLast) return;
    for (int b = 0; b < B; b++) {
        int cb = cnt[b];
        sS[c]  = S[b * C + c];
        sS2[c] = S2[b * C + c];
        __syncthreads();
        const int g0 = (c >> 3) << 3;
        float Sg = 0.0f, S2g = 0.0f;
#pragma unroll
        for (int j = 0; j < 8; j++) { Sg += sS[g0 + j]; S2g += sS2[g0 + j]; }
        float count = (float)cb * 8.0f;
        float ic  = 1.0f / (count + EPS);
        float mu  = Sg * ic;
        float var = (S2g - 2.0f * mu * Sg + count * mu * mu) * ic;
        meanA[b * C + c] = mu;
        istdA[b * C + c] = 1.0f / sqrtf(var + EPS);
        S[b * C + c]  = 0.0f;
        S2[b * C + c] = 0.0f;
        if (c == 0) cnt[b] = 0;
        __syncthreads();
    }
    if (c == 0) g_done = 0;
}

// grid = N, block = 256: out_half = silu((x - mean)*istd*w + b), row-major
__global__ void gn_norm_silu(const float* __restrict__ x, const int* __restrict__ bid,
                             const float* __restrict__ meanA, const float* __restrict__ istdA,
                             const float* __restrict__ w, const float* __restrict__ bb,
                             __half* __restrict__ out) {
    const int i = blockIdx.x;
    const int c = threadIdx.x;
    const int b = bid[i];
    float v = x[(size_t)i * C + c];
    float z = (v - meanA[b * C + c]) * istdA[b * C + c] * w[c] + bb[c];
    out[(size_t)i * C + c] = __float2half_rn(silu(z));
}

// ---------------- CSR build ----------------
__global__ void csr_deg(const int* __restrict__ ei, int* deg) {
    int e = blockIdx.x * 256 + threadIdx.x;
    if (e < E_EDGES) atomicAdd(&deg[ei[e]], 1);
}
__global__ void scan1(const int* __restrict__ deg, int* rp, int* bsum) {
    __shared__ int sm[256];
    int t = threadIdx.x;
    int i = blockIdx.x * 256 + t;
    int v = deg[i];
    sm[t] = v;
    __syncthreads();
    for (int off = 1; off < 256; off <<= 1) {
        int add = (t >= off) ? sm[t - off] : 0;
        __syncthreads();
        sm[t] += add;
        __syncthreads();
    }
    rp[i] = sm[t] - v;
    if (t == 255) bsum[blockIdx.x] = sm[255];
}
__global__ void scan2(int* bsum) {
    __shared__ int sm[256];
    int t = threadIdx.x;
    int v = bsum[t];
    sm[t] = v;
    __syncthreads();
    for (int off = 1; off < 256; off <<= 1) {
        int add = (t >= off) ? sm[t - off] : 0;
        __syncthreads();
        sm[t] += add;
        __syncthreads();
    }
    bsum[t] = sm[t] - v;
}
__global__ void scan3(int* rp, const int* __restrict__ bsum) {
    int i = blockIdx.x * 256 + threadIdx.x;
    rp[i] += bsum[blockIdx.x];
}
__global__ void csr_fill(const int* __restrict__ ei, const int* __restrict__ et,
                         const int* __restrict__ rp, int* fill, unsigned* ct) {
    int e = blockIdx.x * 256 + threadIdx.x;
    if (e < E_EDGES) {
        int row = ei[e];
        int col = ei[E_EDGES + e];
        int t   = et[e];
        int pos = rp[row] + atomicAdd(&fill[row], 1);
        ct[pos] = (unsigned)col | ((unsigned)t << 16);
    }
}

// ---------------- emb projection ----------------
__global__ void emb_proj(const float* __restrict__ emb, const float* __restrict__ ew,
                         const float* __restrict__ eb, float* __restrict__ out) {
    __shared__ float se[EMB];
    const int b = blockIdx.x;
    const int o = threadIdx.x;
    for (int k = o; k < EMB; k += 256) se[k] = silu(emb[b * EMB + k]);
    __syncthreads();
    float acc = eb[o];
#pragma unroll 8
    for (int k = 0; k < EMB; k++) acc += se[k] * ew[k * C + o];
    out[b * C + o] = acc;
}

// ---------------- GEMM: Y[N,1792] = hh[N,256] @ Wh^T + TB[nt[row]] ----------------
// fp16 in, fp32 acc; ldmatrix fragments; 2-stage cp.async pipeline; SW128 XOR swizzle.
#define KC 64            /* K chunk (halves); 128 B per row */
#define STAGE_BYTES 32768 /* As(16K) + Bs(16K) per stage */
#define SMEM_DYN (2 * STAGE_BYTES + NNT * 128 * 4)

__global__ void __launch_bounds__(256, 2)
gemm_fp16(const __half* __restrict__ hh, const __half* __restrict__ Wh,
          const float* __restrict__ TB, const int* __restrict__ ntype,
          __half* __restrict__ Y) {
    extern __shared__ __align__(128) char smem[];
    const uint32_t sbase = smem_u32(smem);
    float* TBs = (float*)(smem + 2 * STAGE_BYTES);

    const int tid  = threadIdx.x;
    const int lane = tid & 31;
    const int warp = tid >> 5;
    const int wm = warp & 3, wn = warp >> 2;

    const int rowBase = blockIdx.y * 128;
    const int nBase   = blockIdx.x * 128;
    const int tEdge   = blockIdx.x >> 1;
    const int oInT    = (blockIdx.x & 1) * 128;

    for (int idx = tid; idx < NNT * 128; idx += 256) {
        TBs[idx] = TB[(size_t)(tEdge * NNT + (idx >> 7)) * C + oInT + (idx & 127)];
    }

    float acc[2][8][4];
#pragma unroll
    for (int a = 0; a < 2; a++)
#pragma unroll
        for (int b2 = 0; b2 < 8; b2++)
#pragma unroll
            for (int c2 = 0; c2 < 4; c2++) acc[a][b2][c2] = 0.0f;

    // loader geometry: thread -> (row lr, 4 x 16B segments)
    const int lr    = tid & 127;
    const int hseg  = tid >> 7;            // 0/1 -> segs 0-3 / 4-7
    const uint32_t swrow = (uint32_t)((lr & 7) << 3);
    const __half* gA = hh + (size_t)(rowBase + lr) * C;
    const __half* gB = Wh + (size_t)(nBase + lr) * C;
    uint32_t soffs[4];
#pragma unroll
    for (int q = 0; q < 4; q++) {
        int s = hseg * 4 + q;
        soffs[q] = (uint32_t)(lr * (KC * 2)) + (uint32_t)(((s * 8) ^ swrow) * 2);
    }

    // ldmatrix per-lane geometry (relative to stage base)
    const int dr = ((lane >> 3) & 1) * 8 + (lane & 7);
    const int dk = (lane >> 4) << 3;
    uint32_t aoff[2], swa[2];
#pragma unroll
    for (int mf = 0; mf < 2; mf++) {
        int r = wm * 32 + mf * 16 + dr;
        aoff[mf] = (uint32_t)(r * (KC * 2));
        swa[mf]  = (uint32_t)((r & 7) << 3);
    }
    uint32_t boff[4], swb[4];
#pragma unroll
    for (int p = 0; p < 4; p++) {
        int n = wn * 64 + p * 16 + dr;
        boff[p] = (uint32_t)(16384 + n * (KC * 2));
        swb[p]  = (uint32_t)((n & 7) << 3);
    }

    // ---- preload chunk 0 into stage 0 ----
    {
        const int k0 = 0;
#pragma unroll
        for (int q = 0; q < 4; q++) {
            int s = hseg * 4 + q;
            cpa16(sbase + soffs[q],         gA + k0 + s * 8);
            cpa16(sbase + 16384 + soffs[q], gB + k0 + s * 8);
        }
        asm volatile("cp.async.commit_group;");
    }

    const int NCHUNK = C / KC;  // 4
    for (int c = 0; c < NCHUNK; c++) {
        const int st = c & 1;
        const uint32_t stb = sbase + (uint32_t)(st * STAGE_BYTES);

        if (c + 1 < NCHUNK) {
            const int k0 = (c + 1) * KC;
            const uint32_t nstb = sbase + (uint32_t)(((c + 1) & 1) * STAGE_BYTES);
#pragma unroll
            for (int q = 0; q < 4; q++) {
                int s = hseg * 4 + q;
                cpa16(nstb + soffs[q],         gA + k0 + s * 8);
                cpa16(nstb + 16384 + soffs[q], gB + k0 + s * 8);
            }
            asm volatile("cp.async.commit_group;");
            asm volatile("cp.async.wait_group 1;");
        } else {
            asm volatile("cp.async.wait_group 0;");
        }
        __syncthreads();

#pragma unroll
        for (int kk = 0; kk < KC; kk += 16) {
            uint32_t af[2][4];
#pragma unroll
            for (int mf = 0; mf < 2; mf++) {
                uint32_t addr = stb + aoff[mf] + (uint32_t)((((kk + dk) ^ swa[mf])) * 2);
                ldsm4(af[mf][0], af[mf][1], af[mf][2], af[mf][3], addr);
            }
            uint32_t bf[4][4];
#pragma unroll
            for (int p = 0; p < 4; p++) {
                uint32_t addr = stb + boff[p] + (uint32_t)((((kk + dk) ^ swb[p])) * 2);
                ldsm4(bf[p][0], bf[p][1], bf[p][2], bf[p][3], addr);
            }
#pragma unroll
            for (int mf = 0; mf < 2; mf++)
#pragma unroll
                for (int nf = 0; nf < 8; nf++) {
                    int p = nf >> 1, o = nf & 1;
                    mma16(acc[mf][nf], af[mf], bf[p][o], bf[p][o + 2]);
                }
        }
        __syncthreads();   // all warps done reading stage st before it is overwritten
    }

    // epilogue: add one-hot bias table, store fp16
    const int gID = lane >> 2, tig = lane & 3;
#pragma unroll
    for (int mf = 0; mf < 2; mf++) {
        int rLo = rowBase + wm * 32 + mf * 16 + gID;
        int rHi = rLo + 8;
        int ntLo = ntype[rLo];
        int ntHi = ntype[rHi];
#pragma unroll
        for (int nf = 0; nf < 8; nf++) {
            int colL = wn * 64 + nf * 8 + tig * 2;
            int colG = nBase + colL;
            __half2 lo = __floats2half2_rn(acc[mf][nf][0] + TBs[ntLo * 128 + colL],
                                           acc[mf][nf][1] + TBs[ntLo * 128 + colL + 1]);
            __half2 hi = __floats2half2_rn(acc[mf][nf][2] + TBs[ntHi * 128 + colL],
                                           acc[mf][nf][3] + TBs[ntHi * 128 + colL + 1]);
            *(__half2*)&Y[(size_t)rLo * NCOLS + colG] = lo;
            *(__half2*)&Y[(size_t)rHi * NCOLS + colG] = hi;
        }
    }
}

// ---------------- gather: out[i,c] = base + sum_e Y[col_e, t_e*256+c] ----------------
__global__ void gather_add(const __half* __restrict__ Y, const int* __restrict__ rp,
                           const int* __restrict__ deg, const unsigned* __restrict__ ct,
                           const int* __restrict__ bid,
                           const float* __restrict__ addB,
                           const float* __restrict__ addN,
                           float* __restrict__ out) {
    const int i  = blockIdx.x;
    const int c0 = threadIdx.x * 4;
    const int s = rp[i];
    const int d = deg[i];
    float4 acc;
    if (addB) acc = *(const float4*)(addB + bid[i] * C + c0);
    else      acc = *(const float4*)(addN + (size_t)i * C + c0);
    int e = s;
    for (; e + 1 < s + d; e += 2) {
        unsigned p0 = ct[e], p1 = ct[e + 1];
        uint2 v0 = *(const uint2*)(Y + (size_t)(p0 & 0xFFFF) * NCOLS + (p0 >> 16) * C + c0);
        uint2 v1 = *(const uint2*)(Y + (size_t)(p1 & 0xFFFF) * NCOLS + (p1 >> 16) * C + c0);
        float2 f;
        f = __half22float2(*(__half2*)&v0.x); acc.x += f.x; acc.y += f.y;
        f = __half22float2(*(__half2*)&v0.y); acc.z += f.x; acc.w += f.y;
        f = __half22float2(*(__half2*)&v1.x); acc.x += f.x; acc.y += f.y;
        f = __half22float2(*(__half2*)&v1.y); acc.z += f.x; acc.w += f.y;
    }
    if (e < s + d) {
        unsigned p = ct[e];
        uint2 v = *(const uint2*)(Y + (size_t)(p & 0xFFFF) * NCOLS + (p >> 16) * C + c0);
        float2 f;
        f = __half22float2(*(__half2*)&v.x); acc.x += f.x; acc.y += f.y;
        f = __half22float2(*(__half2*)&v.y); acc.z += f.x; acc.w += f.y;
    }
    *(float4*)(out + (size_t)i * C + c0) = acc;
}

// ---------------- host ----------------
extern "C" void kernel_launch(void* const* d_in, const int* in_sizes, int n_in,
                              void* d_out, int out_size) {
    const float* x       = (const float*)d_in[0];
    const float* emb     = (const float*)d_in[1];
    const int*   bid     = (const int*)d_in[2];
    const int*   ei      = (const int*)d_in[3];
    const int*   et      = (const int*)d_in[4];
    const int*   ntype   = (const int*)d_in[5];
    const float* gn1_w   = (const float*)d_in[6];
    const float* gn1_b   = (const float*)d_in[7];
    const float* conv1_w = (const float*)d_in[8];
    const float* emb_w   = (const float*)d_in[9];
    const float* emb_b   = (const float*)d_in[10];
    const float* gn2_w   = (const float*)d_in[11];
    const float* gn2_b   = (const float*)d_in[12];
    const float* conv2_w = (const float*)d_in[13];
    float* out = (float*)d_out;

    float *S, *S2, *meanA, *istdA, *h2, *embO, *TBa;
    __half *hh, *Y, *Wha;
    int *cnt, *deg, *fill, *rp, *bsum;
    unsigned* ct;
    cudaGetSymbolAddress((void**)&S,     g_S);
    cudaGetSymbolAddress((void**)&S2,    g_S2);
    cudaGetSymbolAddress((void**)&cnt,   g_cnt);
    cudaGetSymbolAddress((void**)&meanA, g_mean);
    cudaGetSymbolAddress((void**)&istdA, g_istd);
    cudaGetSymbolAddress((void**)&hh,    g_hh);
    cudaGetSymbolAddress((void**)&h2,    g_h2);
    cudaGetSymbolAddress((void**)&Y,     g_Y);
    cudaGetSymbolAddress((void**)&Wha,   g_Wh);
    cudaGetSymbolAddress((void**)&TBa,   g_TB);
    cudaGetSymbolAddress((void**)&embO,  g_emb);
    cudaGetSymbolAddress((void**)&deg,   g_deg);
    cudaGetSymbolAddress((void**)&fill,  g_fill);
    cudaGetSymbolAddress((void**)&rp,    g_rp);
    cudaGetSymbolAddress((void**)&bsum,  g_bsum);
    cudaGetSymbolAddress((void**)&ct,    g_ct);

    __half* Wh1 = Wha;
    __half* Wh2 = Wha + (size_t)NCOLS * C;
    float*  TB1 = TBa;
    float*  TB2 = TBa + NET * NNT * C;

    cudaFuncSetAttribute(gemm_fp16, cudaFuncAttributeMaxDynamicSharedMemorySize, SMEM_DYN);

    dim3 wgrid(9, 56), wblk(32, 8);
    dim3 ggrid(NCOLS / 128, N_NODES / 128);  // (14, 512)

    build_w<<<wgrid, wblk>>>(conv1_w, Wh1, TB1);                               // 0
    gn_stats_f<<<512, 256>>>(x, bid, S, S2, cnt, meanA, istdA);                // 1
    gn_norm_silu<<<N_NODES, 256>>>(x, bid, meanA, istdA, gn1_w, gn1_b, hh);    // 2
    gemm_fp16<<<ggrid, 256, SMEM_DYN>>>(hh, Wh1, TB1, ntype, Y);               // 3
    zero_df<<<N_NODES / 256, 256>>>(deg, fill);                                // 4
    csr_deg<<<E_EDGES / 256, 256>>>(ei, deg);                                  // 5
    scan1<<<256, 256>>>(deg, rp, bsum);                                        // 6
    scan2<<<1, 256>>>(bsum);                                                   // 7
    scan3<<<256, 256>>>(rp, bsum);                                             // 8
    csr_fill<<<E_EDGES / 256, 256>>>(ei, et, rp, fill, ct);                    // 9
    emb_proj<<<B, 256>>>(emb, emb_w, emb_b, embO);                             // 10
    gather_add<<<N_NODES, 64>>>(Y, rp, deg, ct, bid, embO, nullptr, h2);       // 11
    gn_stats_f<<<512, 256>>>(h2, bid, S, S2, cnt, meanA, istdA);               // 12
    gn_norm_silu<<<N_NODES, 256>>>(h2, bid, meanA, istdA, gn2_w, gn2_b, hh);   // 13
    build_w<<<wgrid, wblk>>>(conv2_w, Wh2, TB2);                               // 14
    gemm_fp16<<<ggrid, 256, SMEM_DYN>>>(hh, Wh2, TB2, ntype, Y);               // 15
    gather_add<<<N_NODES, 64>>>(Y, rp, deg, ct, bid, nullptr, x, out);         // 16

    (void)in_sizes; (void)n_in; (void)out_size;
}